// round 4
// baseline (speedup 1.0000x reference)
#include <cuda_runtime.h>
#include <cuda_bf16.h>
#include <math.h>

// Problem constants
#define B 2
#define N 1024
#define G0 40            // coarse grid per axis
#define DHW 128          // fine grid per axis
#define INV_ALPHA 200.0f // 1/0.005
#define BETA 0.01f

// ---------------- scratch (device globals; no allocations allowed) ----------
__device__ float  g_E0[B * N * G0];       // [b][n][i]  exp(-(a_i-c0)^2/alpha)
__device__ float  g_E1[B * G0 * N];       // [b][j][n]
__device__ float  g_E2[B * G0 * N];       // [b][k][n]
__device__ float  g_vals[B * 3 * N];      // [b][c][n]  = -offsets
__device__ float4 g_F[B * G0 * G0 * G0];  // [b][k][j][i] -> {f0,f1,f2,pad}

// ---------------- Kernel 0: per-axis exp tables -----------------------------
__global__ void table_kernel(const float* __restrict__ cpc,
                             const float* __restrict__ cpo) {
    int t = blockIdx.x * blockDim.x + threadIdx.x;
    if (t >= B * N) return;
    int b = t >> 10;
    int n = t & (N - 1);

    float o0 = cpo[t * 3 + 0], o1 = cpo[t * 3 + 1], o2 = cpo[t * 3 + 2];
    float c0 = cpc[t * 3 + 0] + o0;
    float c1 = cpc[t * 3 + 1] + o1;
    float c2 = cpc[t * 3 + 2] + o2;

    g_vals[(b * 3 + 0) * N + n] = -o0;
    g_vals[(b * 3 + 1) * N + n] = -o1;
    g_vals[(b * 3 + 2) * N + n] = -o2;

    const float step = 2.0f / (float)(G0 - 1);
#pragma unroll 8
    for (int i = 0; i < G0; i++) {
        float a = fmaf((float)i, step, -1.0f);
        float d0 = a - c0, d1 = a - c1, d2 = a - c2;
        g_E0[(b * N + n) * G0 + i] = expf(-d0 * d0 * INV_ALPHA);
        g_E1[(b * G0 + i) * N + n] = expf(-d1 * d1 * INV_ALPHA);
        g_E2[(b * G0 + i) * N + n] = expf(-d2 * d2 * INV_ALPHA);
    }
}

// ---------------- Kernel A: coarse displacement field -----------------------
// One block per (jt, k, b); 160 threads = (i in [0,40)) x (jl in [0,4)).
// F[b][k][j][i][c] = 1.01 * sum_n(E0*E1*E2*v_c) / (sum_n(E0*E1*E2) + beta)
#define SWS 1028  // padded stride to avoid 4KB-apart bank conflicts
__global__ __launch_bounds__(160) void coarse_kernel() {
    __shared__ float sW[4 * SWS];   // sW[jl][n] = E1[j][n]*E2[k][n]
    __shared__ float sV0[N], sV1[N], sV2[N];

    int jt = blockIdx.x;   // 0..9
    int k  = blockIdx.y;   // 0..39
    int b  = blockIdx.z;   // 0..1
    int tid = threadIdx.x; // 0..159

    const float* E1b = &g_E1[(b * G0) * N];
    const float* E2k = &g_E2[(b * G0 + k) * N];
    const float* Vb  = &g_vals[b * 3 * N];

    for (int n = tid; n < N; n += 160) {
        float e2 = E2k[n];
#pragma unroll
        for (int jl = 0; jl < 4; jl++)
            sW[jl * SWS + n] = E1b[(jt * 4 + jl) * N + n] * e2;
        sV0[n] = Vb[n];
        sV1[n] = Vb[N + n];
        sV2[n] = Vb[2 * N + n];
    }
    __syncthreads();

    int i  = tid % 40;
    int jl = tid / 40;
    int j  = jt * 4 + jl;

    const float* E0row = &g_E0[(b * N) * G0 + i];  // stride G0 over n
    const float* sWrow = &sW[jl * SWS];

    float s = 0.f, a0 = 0.f, a1 = 0.f, a2 = 0.f;
#pragma unroll 8
    for (int n = 0; n < N; n++) {
        float w = E0row[n * G0] * sWrow[n];
        s  += w;
        a0 = fmaf(w, sV0[n], a0);
        a1 = fmaf(w, sV1[n], a1);
        a2 = fmaf(w, sV2[n], a2);
    }
    float inv = (BETA + 1.0f) / (s + BETA);
    float4 r;
    r.x = a0 * inv; r.y = a1 * inv; r.z = a2 * inv; r.w = 0.f;
    g_F[((b * G0 + k) * G0 + j) * G0 + i] = r;
}

// ---------------- Kernel B: upsample flow + grid_sample ----------------------
__global__ __launch_bounds__(256) void warp_kernel(const float* __restrict__ mask,
                                                   float* __restrict__ out) {
    int idx = blockIdx.x * blockDim.x + threadIdx.x; // 0 .. 2*128^3-1
    int e = idx & 127;          // w index (fastest)
    int h = (idx >> 7) & 127;   // h index
    int d = (idx >> 14) & 127;  // d index
    int b = idx >> 21;

    // ---- coarse coordinates (F.interpolate align_corners=False) ----
    const float scale = (float)G0 / (float)DHW;  // 0.3125 exact
    float ck = fmaxf(((float)d + 0.5f) * scale - 0.5f, 0.0f);
    float cj = fmaxf(((float)h + 0.5f) * scale - 0.5f, 0.0f);
    float ci = fmaxf(((float)e + 0.5f) * scale - 0.5f, 0.0f);

    int k0 = min((int)ck, G0 - 1); int k1 = min(k0 + 1, G0 - 1); float fk = ck - (float)k0;
    int j0 = min((int)cj, G0 - 1); int j1 = min(j0 + 1, G0 - 1); float fj = cj - (float)j0;
    int i0 = min((int)ci, G0 - 1); int i1 = min(i0 + 1, G0 - 1); float fi = ci - (float)i0;

    const float4* Fb = &g_F[b * G0 * G0 * G0];
    int bk0 = k0 * G0, bk1 = k1 * G0;

    float4 v000 = Fb[(bk0 + j0) * G0 + i0];
    float4 v001 = Fb[(bk0 + j0) * G0 + i1];
    float4 v010 = Fb[(bk0 + j1) * G0 + i0];
    float4 v011 = Fb[(bk0 + j1) * G0 + i1];
    float4 v100 = Fb[(bk1 + j0) * G0 + i0];
    float4 v101 = Fb[(bk1 + j0) * G0 + i1];
    float4 v110 = Fb[(bk1 + j1) * G0 + i0];
    float4 v111 = Fb[(bk1 + j1) * G0 + i1];

    float gi = 1.0f - fi, gj = 1.0f - fj, gk = 1.0f - fk;
    float w00 = gj * gk, w01 = gj * fk, w10 = fj * gk, w11 = fj * fk;

    float f0 = gi * (w00 * v000.x + w10 * v010.x + w01 * v100.x + w11 * v110.x)
             + fi * (w00 * v001.x + w10 * v011.x + w01 * v101.x + w11 * v111.x);
    float f1 = gi * (w00 * v000.y + w10 * v010.y + w01 * v100.y + w11 * v110.y)
             + fi * (w00 * v001.y + w10 * v011.y + w01 * v101.y + w11 * v111.y);
    float f2 = gi * (w00 * v000.z + w10 * v010.z + w01 * v100.z + w11 * v110.z)
             + fi * (w00 * v001.z + w10 * v011.z + w01 * v101.z + w11 * v111.z);

    // ---- warped grid coords (base + flow), then to sample space ----
    const float lstep = 2.0f / (float)(DHW - 1);
    float gx = fmaf((float)e, lstep, -1.0f) + f0;
    float gy = fmaf((float)h, lstep, -1.0f) + f1;
    float gz = fmaf((float)d, lstep, -1.0f) + f2;

    // x = ((gx+1)*W - 1)/2 = gx*64 + 63.5
    float x = fmaf(gx, 64.0f, 63.5f);
    float y = fmaf(gy, 64.0f, 63.5f);
    float z = fmaf(gz, 64.0f, 63.5f);

    int ix = (int)floorf(x); float fx = x - (float)ix;
    int iy = (int)floorf(y); float fy = y - (float)iy;
    int iz = (int)floorf(z); float fz = z - (float)iz;

    const float* mb = mask + b * (DHW * DHW * DHW);

    float qx = 1.0f - fx, qy = 1.0f - fy, qz = 1.0f - fz;

    float acc = 0.0f;
#pragma unroll
    for (int dz = 0; dz < 2; dz++) {
        int zi = iz + dz;
        if ((unsigned)zi >= (unsigned)DHW) continue;
        float wz = dz ? fz : qz;
        const float* mz = mb + (zi << 14);
#pragma unroll
        for (int dy = 0; dy < 2; dy++) {
            int yi = iy + dy;
            if ((unsigned)yi >= (unsigned)DHW) continue;
            float wzy = wz * (dy ? fy : qy);
            const float* mzy = mz + (yi << 7);
#pragma unroll
            for (int dx = 0; dx < 2; dx++) {
                int xi = ix + dx;
                if ((unsigned)xi >= (unsigned)DHW) continue;
                acc = fmaf(wzy * (dx ? fx : qx), mzy[xi], acc);
            }
        }
    }
    out[idx] = acc;
}

// ---------------- launch ------------------------------------------------------
extern "C" void kernel_launch(void* const* d_in, const int* in_sizes, int n_in,
                              void* d_out, int out_size) {
    const float* mask = (const float*)d_in[0];  // (2,1,128,128,128)
    const float* cpc  = (const float*)d_in[1];  // (2,1024,3)
    const float* cpo  = (const float*)d_in[2];  // (2,1024,3)
    float* out = (float*)d_out;                 // (2,1,128,128,128)

    table_kernel<<<(B * N + 255) / 256, 256>>>(cpc, cpo);
    coarse_kernel<<<dim3(G0 / 4, G0, B), 160>>>();
    int total = B * DHW * DHW * DHW;
    warp_kernel<<<total / 256, 256>>>(mask, out);
}

// round 7
// speedup vs baseline: 2.1177x; 2.1177x over previous
#include <cuda_runtime.h>
#include <cuda_bf16.h>
#include <math.h>

// Problem constants
#define B 2
#define N 1024
#define G0 40            // coarse grid per axis
#define DHW 128          // fine grid per axis
#define INV_ALPHA 200.0f // 1/0.005
#define BETA 0.01f
#define T2 1e-10f        // weight cutoff: E2*max(E1) <= T2 -> term dropped

// ---------------- scratch (device globals; no allocations allowed) ----------
__device__ float  g_E0[B * N * G0];       // [b][n][i]  exp(-(a_i-c0)^2/alpha)
__device__ float  g_E1[B * G0 * N];       // [b][j][n]
__device__ float  g_E2[B * G0 * N];       // [b][k][n]
__device__ float  g_vals[B * 3 * N];      // [b][c][n]  = -offsets
__device__ float4 g_F[B * G0 * G0 * G0];  // [b][k][j][i] -> {f0,f1,f2,pad}

// ---------------- Kernel 0: per-axis exp tables (1 thread per (b,n,i)) ------
__global__ __launch_bounds__(256) void table_kernel(const float* __restrict__ cpc,
                                                    const float* __restrict__ cpo) {
    int idx = blockIdx.x * 256 + threadIdx.x;   // 0 .. B*N*G0-1 = 81919
    if (idx >= B * N * G0) return;
    int i = idx % G0;
    int t = idx / G0;        // b*N + n
    int b = t >> 10;
    int n = t & (N - 1);

    float o0 = cpo[t * 3 + 0], o1 = cpo[t * 3 + 1], o2 = cpo[t * 3 + 2];
    float c0 = cpc[t * 3 + 0] + o0;
    float c1 = cpc[t * 3 + 1] + o1;
    float c2 = cpc[t * 3 + 2] + o2;

    if (i == 0) {
        g_vals[(b * 3 + 0) * N + n] = -o0;
        g_vals[(b * 3 + 1) * N + n] = -o1;
        g_vals[(b * 3 + 2) * N + n] = -o2;
    }

    const float step = 2.0f / (float)(G0 - 1);
    float a = fmaf((float)i, step, -1.0f);
    float d0 = a - c0, d1 = a - c1, d2 = a - c2;
    g_E0[(b * N + n) * G0 + i] = __expf(-d0 * d0 * INV_ALPHA);
    g_E1[(b * G0 + i) * N + n] = __expf(-d1 * d1 * INV_ALPHA);
    g_E2[(b * G0 + i) * N + n] = __expf(-d2 * d2 * INV_ALPHA);
}

// ---------------- Kernel A: sparse coarse displacement field -----------------
// One block per (jt, k, b). 256 threads.
// Phase 1 (all 8 warps): deterministically compact landmarks whose combined
//   y/z Gaussian weight can exceed T2 into smem: {n, v0,v1,v2} + 4 E1*E2 weights.
// Phase 2 (threads 0..159 = i x jl): dense loop over ~140 survivors.
__global__ __launch_bounds__(256) void coarse_kernel() {
    __shared__ float4 sPack[N];       // {n_as_float, v0, v1, v2}
    __shared__ float  sW[4 * N];      // [jl][slot] = E1[j][n]*E2[k][n]
    __shared__ int    sCnt[8];
    __shared__ int    sBase[9];

    int jt = blockIdx.x;   // 0..9
    int k  = blockIdx.y;   // 0..39
    int b  = blockIdx.z;   // 0..1
    int tid  = threadIdx.x;
    int wid  = tid >> 5, lane = tid & 31;

    const float* E2k = &g_E2[(b * G0 + k) * N];
    const float* E1b = &g_E1[(b * G0 + jt * 4) * N];   // jl rows at +jl*N
    const float* Vb  = &g_vals[b * 3 * N];

    // ---- phase A: count survivors per warp-range (order-preserving) ----
    unsigned bal[4];
    int cnt = 0;
#pragma unroll
    for (int it = 0; it < 4; it++) {
        int n = wid * 128 + it * 32 + lane;
        float e2 = E2k[n];
        bool p = false;
        if (e2 > T2) {   // quick reject (E1 <= 1)
            float m = fmaxf(fmaxf(E1b[n], E1b[N + n]),
                            fmaxf(E1b[2 * N + n], E1b[3 * N + n]));
            p = (e2 * m > T2);
        }
        bal[it] = __ballot_sync(0xffffffffu, p);
        cnt += __popc(bal[it]);
    }
    if (lane == 0) sCnt[wid] = cnt;
    __syncthreads();
    if (tid == 0) {
        int acc = 0;
        for (int w = 0; w < 8; w++) { sBase[w] = acc; acc += sCnt[w]; }
        sBase[8] = acc;
    }
    __syncthreads();

    // ---- phase B: ordered compaction ----
    int off = sBase[wid];
#pragma unroll
    for (int it = 0; it < 4; it++) {
        unsigned bl = bal[it];
        if (bl & (1u << lane)) {
            int n = wid * 128 + it * 32 + lane;
            float e2 = E2k[n];
            int slot = off + __popc(bl & ((1u << lane) - 1u));
            float4 pv;
            pv.x = __int_as_float(n);
            pv.y = Vb[n];
            pv.z = Vb[N + n];
            pv.w = Vb[2 * N + n];
            sPack[slot] = pv;
            sW[0 * N + slot] = e2 * E1b[n];
            sW[1 * N + slot] = e2 * E1b[N + n];
            sW[2 * N + slot] = e2 * E1b[2 * N + n];
            sW[3 * N + slot] = e2 * E1b[3 * N + n];
        }
        off += __popc(bl);
    }
    __syncthreads();
    int total = sBase[8];

    // ---- phase C: dense accumulation over survivors ----
    if (tid < 160) {
        int i  = tid % 40;
        int jl = tid / 40;
        const float* E0b  = &g_E0[(size_t)(b * N) * G0 + i];  // index n*G0
        const float* wrow = &sW[jl * N];

        float s = 0.f, a0 = 0.f, a1 = 0.f, a2 = 0.f;
#pragma unroll 4
        for (int t = 0; t < total; t++) {
            float4 pv = sPack[t];
            float  w  = wrow[t] * E0b[__float_as_int(pv.x) * G0];
            s  += w;
            a0 = fmaf(w, pv.y, a0);
            a1 = fmaf(w, pv.z, a1);
            a2 = fmaf(w, pv.w, a2);
        }
        float inv = (BETA + 1.0f) / (s + BETA);
        float4 r;
        r.x = a0 * inv; r.y = a1 * inv; r.z = a2 * inv; r.w = 0.f;
        int j = jt * 4 + jl;
        g_F[((b * G0 + k) * G0 + j) * G0 + i] = r;
    }
}

// ---------------- Kernel B: upsample flow + grid_sample ----------------------
__global__ __launch_bounds__(256) void warp_kernel(const float* __restrict__ mask,
                                                   float* __restrict__ out) {
    int idx = blockIdx.x * blockDim.x + threadIdx.x; // 0 .. 2*128^3-1
    int e = idx & 127;          // w index (fastest)
    int h = (idx >> 7) & 127;   // h index
    int d = (idx >> 14) & 127;  // d index
    int b = idx >> 21;

    // ---- coarse coordinates (F.interpolate align_corners=False) ----
    const float scale = (float)G0 / (float)DHW;  // 0.3125 exact
    float ck = fmaxf(((float)d + 0.5f) * scale - 0.5f, 0.0f);
    float cj = fmaxf(((float)h + 0.5f) * scale - 0.5f, 0.0f);
    float ci = fmaxf(((float)e + 0.5f) * scale - 0.5f, 0.0f);

    int k0 = min((int)ck, G0 - 1); int k1 = min(k0 + 1, G0 - 1); float fk = ck - (float)k0;
    int j0 = min((int)cj, G0 - 1); int j1 = min(j0 + 1, G0 - 1); float fj = cj - (float)j0;
    int i0 = min((int)ci, G0 - 1); int i1 = min(i0 + 1, G0 - 1); float fi = ci - (float)i0;

    const float4* Fb = &g_F[b * G0 * G0 * G0];
    int bk0 = k0 * G0, bk1 = k1 * G0;

    float4 v000 = Fb[(bk0 + j0) * G0 + i0];
    float4 v001 = Fb[(bk0 + j0) * G0 + i1];
    float4 v010 = Fb[(bk0 + j1) * G0 + i0];
    float4 v011 = Fb[(bk0 + j1) * G0 + i1];
    float4 v100 = Fb[(bk1 + j0) * G0 + i0];
    float4 v101 = Fb[(bk1 + j0) * G0 + i1];
    float4 v110 = Fb[(bk1 + j1) * G0 + i0];
    float4 v111 = Fb[(bk1 + j1) * G0 + i1];

    float gi = 1.0f - fi, gj = 1.0f - fj, gk = 1.0f - fk;
    float w00 = gj * gk, w01 = gj * fk, w10 = fj * gk, w11 = fj * fk;

    float f0 = gi * (w00 * v000.x + w10 * v010.x + w01 * v100.x + w11 * v110.x)
             + fi * (w00 * v001.x + w10 * v011.x + w01 * v101.x + w11 * v111.x);
    float f1 = gi * (w00 * v000.y + w10 * v010.y + w01 * v100.y + w11 * v110.y)
             + fi * (w00 * v001.y + w10 * v011.y + w01 * v101.y + w11 * v111.y);
    float f2 = gi * (w00 * v000.z + w10 * v010.z + w01 * v100.z + w11 * v110.z)
             + fi * (w00 * v001.z + w10 * v011.z + w01 * v101.z + w11 * v111.z);

    // ---- warped grid coords (base + flow), then to sample space ----
    const float lstep = 2.0f / (float)(DHW - 1);
    float gx = fmaf((float)e, lstep, -1.0f) + f0;
    float gy = fmaf((float)h, lstep, -1.0f) + f1;
    float gz = fmaf((float)d, lstep, -1.0f) + f2;

    // x = ((gx+1)*W - 1)/2 = gx*64 + 63.5
    float x = fmaf(gx, 64.0f, 63.5f);
    float y = fmaf(gy, 64.0f, 63.5f);
    float z = fmaf(gz, 64.0f, 63.5f);

    int ix = (int)floorf(x); float fx = x - (float)ix;
    int iy = (int)floorf(y); float fy = y - (float)iy;
    int iz = (int)floorf(z); float fz = z - (float)iz;

    const float* mb = mask + b * (DHW * DHW * DHW);

    float qx = 1.0f - fx, qy = 1.0f - fy, qz = 1.0f - fz;

    float acc = 0.0f;
#pragma unroll
    for (int dz = 0; dz < 2; dz++) {
        int zi = iz + dz;
        if ((unsigned)zi >= (unsigned)DHW) continue;
        float wz = dz ? fz : qz;
        const float* mz = mb + (zi << 14);
#pragma unroll
        for (int dy = 0; dy < 2; dy++) {
            int yi = iy + dy;
            if ((unsigned)yi >= (unsigned)DHW) continue;
            float wzy = wz * (dy ? fy : qy);
            const float* mzy = mz + (yi << 7);
#pragma unroll
            for (int dx = 0; dx < 2; dx++) {
                int xi = ix + dx;
                if ((unsigned)xi >= (unsigned)DHW) continue;
                acc = fmaf(wzy * (dx ? fx : qx), mzy[xi], acc);
            }
        }
    }
    out[idx] = acc;
}

// ---------------- launch ------------------------------------------------------
extern "C" void kernel_launch(void* const* d_in, const int* in_sizes, int n_in,
                              void* d_out, int out_size) {
    const float* mask = (const float*)d_in[0];  // (2,1,128,128,128)
    const float* cpc  = (const float*)d_in[1];  // (2,1024,3)
    const float* cpo  = (const float*)d_in[2];  // (2,1024,3)
    float* out = (float*)d_out;                 // (2,1,128,128,128)

    table_kernel<<<(B * N * G0 + 255) / 256, 256>>>(cpc, cpo);
    coarse_kernel<<<dim3(G0 / 4, G0, B), 256>>>();
    int total = B * DHW * DHW * DHW;
    warp_kernel<<<total / 256, 256>>>(mask, out);
}